// round 1
// baseline (speedup 1.0000x reference)
#include <cuda_runtime.h>
#include <cuda_bf16.h>

// Problem constants
#define B_SZ   4096
#define HH     128
#define PHI_D  784
#define H1_D   128
#define H2_D   256
#define WIN    112           // largest patch size
#define WSTRIDE 113          // padded smem stride
#define EPS    1e-5f

// ---------------- scratch (device globals; no allocation allowed) ------------
__device__ float g_phi[B_SZ * PHI_D];
__device__ float g_h1 [B_SZ * H1_D];
__device__ float g_h1w[B_SZ * H1_D];
__device__ float g_h2 [B_SZ * H2_D];
__device__ float g_h2w[B_SZ * H2_D];
__device__ float g_sum1[2 * H1_D];
__device__ float g_sq1 [2 * H1_D];
__device__ float g_sc1 [2 * H1_D];
__device__ float g_sh1 [2 * H1_D];
__device__ float g_sum2[2 * H2_D];
__device__ float g_sq2 [2 * H2_D];
__device__ float g_sc2 [2 * H2_D];
__device__ float g_sh2 [2 * H2_D];

// ---------------- K0: zero stat accumulators --------------------------------
__global__ void zero_stats_kernel() {
    int i = threadIdx.x;                       // 512 threads
    if (i < 256) { g_sum1[i] = 0.f; g_sq1[i] = 0.f; }
    g_sum2[i] = 0.f; g_sq2[i] = 0.f;
}

// ---------------- K1: foveate -> phi (4096 x 784) ----------------------------
// One block per batch element. Cache the 112x112 window (contains all 4 nested
// patches) in shared memory with zero padding, then compute pooled outputs.
__global__ void foveate_kernel(const float* __restrict__ x,
                               const float* __restrict__ loc,
                               float* __restrict__ phi) {
    extern __shared__ float win[];             // WIN * WSTRIDE
    int b = blockIdx.x;
    float lx = loc[2 * b + 0];
    float ly = loc[2 * b + 1];
    int cx = (int)(0.5f * ((lx + 1.0f) * 128.0f));   // truncation == jax astype(int32)
    int cy = (int)(0.5f * ((ly + 1.0f) * 128.0f));
    int wy0 = cy - 56, wx0 = cx - 56;
    const float* xb = x + (size_t)b * HH * HH;

    for (int i = threadIdx.x; i < WIN * WIN; i += blockDim.x) {
        int r = i / WIN, c = i - r * WIN;
        int gy = wy0 + r, gx = wx0 + c;
        float v = 0.f;
        if (gy >= 0 && gy < HH && gx >= 0 && gx < HH) v = xb[gy * HH + gx];
        win[r * WSTRIDE + c] = v;
    }
    __syncthreads();

    for (int o = threadIdx.x; o < PHI_D; o += blockDim.x) {
        int p   = o / 196;
        int rem = o - p * 196;
        int i   = rem / 14;
        int j   = rem - i * 14;
        int k   = 1 << p;                      // 1,2,4,8
        int off = 56 - 7 * k;                  // nested patch offset in window
        int rb  = off + i * k;
        int cb  = off + j * k;
        float s = 0.f;
        for (int di = 0; di < k; di++) {
            const float* row = &win[(rb + di) * WSTRIDE + cb];
            for (int dj = 0; dj < k; dj++) s += row[dj];
        }
        phi[(size_t)b * PHI_D + o] = s * (1.0f / (float)(k * k));
    }
}

// ---------------- K2: GEMM1 h1 = phi @ W1 (bias cancels under BN) ------------
// BM=64, BN=64, BK=16, 256 threads, 4x4 micro-tile. A stored K-major in smem.
__global__ void gemm1_kernel(const float* __restrict__ A,   // (4096,784)
                             const float* __restrict__ W,   // (784,128)
                             float* __restrict__ out) {     // (4096,128)
    __shared__ float As[16][68];
    __shared__ float Bs[16][68];
    int t = threadIdx.x;
    int rowBase = blockIdx.x * 64;
    int colBase = blockIdx.y * 64;
    int ty = t >> 4, tx = t & 15;
    float acc[4][4] = {};

    int lc  = t & 15;            // K index for A load
    int lr  = (t >> 4) << 2;     // 4 M rows
    int bc  = t & 63;            // N index for B load
    int br  = t >> 6;            // 0..3

    for (int k0 = 0; k0 < PHI_D; k0 += 16) {
        #pragma unroll
        for (int rr = 0; rr < 4; rr++)
            As[lc][lr + rr] = A[(size_t)(rowBase + lr + rr) * PHI_D + k0 + lc];
        #pragma unroll
        for (int pp = 0; pp < 4; pp++)
            Bs[br * 4 + pp][bc] = W[(size_t)(k0 + br * 4 + pp) * H1_D + colBase + bc];
        __syncthreads();
        #pragma unroll
        for (int kk = 0; kk < 16; kk++) {
            float4 a = *(const float4*)&As[kk][ty * 4];
            float4 b = *(const float4*)&Bs[kk][tx * 4];
            acc[0][0] += a.x * b.x; acc[0][1] += a.x * b.y; acc[0][2] += a.x * b.z; acc[0][3] += a.x * b.w;
            acc[1][0] += a.y * b.x; acc[1][1] += a.y * b.y; acc[1][2] += a.y * b.z; acc[1][3] += a.y * b.w;
            acc[2][0] += a.z * b.x; acc[2][1] += a.z * b.y; acc[2][2] += a.z * b.z; acc[2][3] += a.z * b.w;
            acc[3][0] += a.w * b.x; acc[3][1] += a.w * b.y; acc[3][2] += a.w * b.z; acc[3][3] += a.w * b.w;
        }
        __syncthreads();
    }
    #pragma unroll
    for (int rr = 0; rr < 4; rr++) {
        int row = rowBase + ty * 4 + rr;
        #pragma unroll
        for (int cc = 0; cc < 4; cc++)
            out[(size_t)row * H1_D + colBase + tx * 4 + cc] = acc[rr][cc];
    }
}

// ---------------- K2w: where path layer1: h1w = loc @ Ww1 --------------------
__global__ void where1_kernel(const float* __restrict__ loc,
                              const float* __restrict__ W,   // (2,128)
                              float* __restrict__ out) {
    int idx = blockIdx.x * blockDim.x + threadIdx.x;         // 524288
    int b = idx >> 7, j = idx & 127;
    out[idx] = loc[2 * b] * W[j] + loc[2 * b + 1] * W[H1_D + j];
}

// ---------------- K3: column stats of h1 / h1w ------------------------------
__global__ void stats1_kernel() {
    int t = threadIdx.x;               // 256
    int base = blockIdx.x * 128;       // 32 blocks x 128 rows
    float s1 = 0, q1 = 0, s2 = 0, q2 = 0;
    for (int it = 0; it < 64; it++) {
        int idx = (base + it * 2) * H1_D + t;   // two rows per iter, coalesced
        float v = g_h1[idx];  s1 += v; q1 += v * v;
        float w = g_h1w[idx]; s2 += w; q2 += w * w;
    }
    int col = t & 127;
    atomicAdd(&g_sum1[col], s1);        atomicAdd(&g_sq1[col], q1);
    atomicAdd(&g_sum1[128 + col], s2);  atomicAdd(&g_sq1[128 + col], q2);
}

__global__ void finalize1_kernel(const float* __restrict__ g1, const float* __restrict__ be1,
                                 const float* __restrict__ gw1, const float* __restrict__ bew1) {
    int j = threadIdx.x;               // 256
    float mean = g_sum1[j] * (1.0f / 4096.0f);
    float var  = g_sq1[j] * (1.0f / 4096.0f) - mean * mean;
    float g  = (j < 128) ? g1[j]  : gw1[j - 128];
    float be = (j < 128) ? be1[j] : bew1[j - 128];
    float sc = g * rsqrtf(var + EPS);
    g_sc1[j] = sc;
    g_sh1[j] = be - mean * sc;
}

// ---------------- K4: GEMM2 (both paths), BN+relu fused on A load ------------
__global__ void gemm2_kernel(const float* __restrict__ W2,    // (128,256)
                             const float* __restrict__ Ww2) { // (128,256)
    __shared__ float As[16][68];
    __shared__ float Bs[16][68];
    int path = blockIdx.z;
    const float* A  = path ? g_h1w : g_h1;
    const float* W  = path ? Ww2   : W2;
    float*       out = path ? g_h2w : g_h2;
    const float* sc = g_sc1 + path * H1_D;
    const float* sh = g_sh1 + path * H1_D;

    int t = threadIdx.x;
    int rowBase = blockIdx.x * 64;
    int colBase = blockIdx.y * 64;
    int ty = t >> 4, tx = t & 15;
    float acc[4][4] = {};

    int lc = t & 15;
    int lr = (t >> 4) << 2;
    int bc = t & 63;
    int br = t >> 6;

    for (int k0 = 0; k0 < H1_D; k0 += 16) {
        int kc = k0 + lc;
        float s = sc[kc], h = sh[kc];
        #pragma unroll
        for (int rr = 0; rr < 4; rr++) {
            float v = A[(size_t)(rowBase + lr + rr) * H1_D + kc];
            As[lc][lr + rr] = fmaxf(v * s + h, 0.f);       // relu(BN(h1))
        }
        #pragma unroll
        for (int pp = 0; pp < 4; pp++)
            Bs[br * 4 + pp][bc] = W[(size_t)(k0 + br * 4 + pp) * H2_D + colBase + bc];
        __syncthreads();
        #pragma unroll
        for (int kk = 0; kk < 16; kk++) {
            float4 a = *(const float4*)&As[kk][ty * 4];
            float4 b = *(const float4*)&Bs[kk][tx * 4];
            acc[0][0] += a.x * b.x; acc[0][1] += a.x * b.y; acc[0][2] += a.x * b.z; acc[0][3] += a.x * b.w;
            acc[1][0] += a.y * b.x; acc[1][1] += a.y * b.y; acc[1][2] += a.y * b.z; acc[1][3] += a.y * b.w;
            acc[2][0] += a.z * b.x; acc[2][1] += a.z * b.y; acc[2][2] += a.z * b.z; acc[2][3] += a.z * b.w;
            acc[3][0] += a.w * b.x; acc[3][1] += a.w * b.y; acc[3][2] += a.w * b.z; acc[3][3] += a.w * b.w;
        }
        __syncthreads();
    }
    #pragma unroll
    for (int rr = 0; rr < 4; rr++) {
        int row = rowBase + ty * 4 + rr;
        #pragma unroll
        for (int cc = 0; cc < 4; cc++)
            out[(size_t)row * H2_D + colBase + tx * 4 + cc] = acc[rr][cc];
    }
}

// ---------------- K5: column stats of h2 / h2w ------------------------------
__global__ void stats2_kernel() {
    int t = threadIdx.x;               // 256
    int base = blockIdx.x * 128;       // 32 blocks x 128 rows
    float s1 = 0, q1 = 0, s2 = 0, q2 = 0;
    for (int it = 0; it < 128; it++) {
        int idx = (base + it) * H2_D + t;
        float v = g_h2[idx];  s1 += v; q1 += v * v;
        float w = g_h2w[idx]; s2 += w; q2 += w * w;
    }
    atomicAdd(&g_sum2[t], s1);        atomicAdd(&g_sq2[t], q1);
    atomicAdd(&g_sum2[256 + t], s2);  atomicAdd(&g_sq2[256 + t], q2);
}

__global__ void finalize2_kernel(const float* __restrict__ g2, const float* __restrict__ be2,
                                 const float* __restrict__ gw2, const float* __restrict__ bew2) {
    int j = threadIdx.x;               // 512
    float mean = g_sum2[j] * (1.0f / 4096.0f);
    float var  = g_sq2[j] * (1.0f / 4096.0f) - mean * mean;
    float g  = (j < 256) ? g2[j]  : gw2[j - 256];
    float be = (j < 256) ? be2[j] : bew2[j - 256];
    float sc = g * rsqrtf(var + EPS);
    g_sc2[j] = sc;
    g_sh2[j] = be - mean * sc;
}

// ---------------- K6: out = relu(BN(h2) + BN(h2w)) ---------------------------
__global__ void final_kernel(float* __restrict__ out) {
    int idx = blockIdx.x * blockDim.x + threadIdx.x;   // 1048576
    int c = idx & 255;
    float a = g_h2[idx]  * g_sc2[c]       + g_sh2[c];
    float b = g_h2w[idx] * g_sc2[256 + c] + g_sh2[256 + c];
    out[idx] = fmaxf(a + b, 0.f);
}

// ---------------- launch -----------------------------------------------------
extern "C" void kernel_launch(void* const* d_in, const int* in_sizes, int n_in,
                              void* d_out, int out_size) {
    const float* x        = (const float*)d_in[0];
    const float* loc      = (const float*)d_in[1];
    const float* what_W1  = (const float*)d_in[2];
    const float* what_g1  = (const float*)d_in[4];
    const float* what_be1 = (const float*)d_in[5];
    const float* what_W2  = (const float*)d_in[6];
    const float* what_g2  = (const float*)d_in[8];
    const float* what_be2 = (const float*)d_in[9];
    const float* where_W1  = (const float*)d_in[10];
    const float* where_g1  = (const float*)d_in[12];
    const float* where_be1 = (const float*)d_in[13];
    const float* where_W2  = (const float*)d_in[14];
    const float* where_g2  = (const float*)d_in[16];
    const float* where_be2 = (const float*)d_in[17];
    float* out = (float*)d_out;

    // phi device pointers resolved via symbols inside kernels; get raw ptrs for args
    static float* p_phi = nullptr;
    static float* p_h1 = nullptr;
    static float* p_h1w = nullptr;
    if (!p_phi) {
        cudaGetSymbolAddress((void**)&p_phi, g_phi);
        cudaGetSymbolAddress((void**)&p_h1, g_h1);
        cudaGetSymbolAddress((void**)&p_h1w, g_h1w);
    }

    const int FOV_SMEM = WIN * WSTRIDE * sizeof(float);   // 50624 B > 48KB
    cudaFuncSetAttribute(foveate_kernel,
                         cudaFuncAttributeMaxDynamicSharedMemorySize, FOV_SMEM);

    zero_stats_kernel<<<1, 512>>>();
    foveate_kernel<<<B_SZ, 256, FOV_SMEM>>>(x, loc, p_phi);
    where1_kernel<<<(B_SZ * H1_D) / 512, 512>>>(loc, where_W1, p_h1w);
    gemm1_kernel<<<dim3(B_SZ / 64, H1_D / 64), 256>>>(p_phi, what_W1, p_h1);
    stats1_kernel<<<32, 256>>>();
    finalize1_kernel<<<1, 256>>>(what_g1, what_be1, where_g1, where_be1);
    gemm2_kernel<<<dim3(B_SZ / 64, H2_D / 64, 2), 256>>>(what_W2, where_W2);
    stats2_kernel<<<32, 256>>>();
    finalize2_kernel<<<1, 512>>>(what_g2, what_be2, where_g2, where_be2);
    final_kernel<<<(B_SZ * H2_D) / 512, 512>>>(out);
}